// round 13
// baseline (speedup 1.0000x reference)
#include <cuda_runtime.h>
#include <cuda_fp16.h>
#include <cstdint>

// Problem sizes (fixed)
#define MDIM 2048
#define NDIM 4096
#define KDIM 4096
// Tiling
#define MT 128        // CTA tile M
#define NT 256        // CTA tile N
#define KC 64         // K-chunk (halves) = 128B per smem row
#define NCHUNK (KDIM / KC)   // 64 (== number of K slices)
#define STAGES 3
#define THREADS 512
#define GRID 148              // 1 CTA/SM, co-resident on 148- and 152-SM parts
#define TARGET 148            // flag arrivals per slice
#define NTILES ((MDIM / MT) * (NDIM / NT))   // 256

// Scratch + flags (allocation-free rule: __device__ globals)
__device__ __half g_xh[(size_t)MDIM * KDIM];  // 16 MB
__device__ __half g_wh[(size_t)NDIM * KDIM];  // 32 MB
__device__ int    g_flag[NCHUNK];

// ---------------- helpers ----------------
__device__ __forceinline__ uint32_t smem_u32(const void* p) {
    uint32_t a;
    asm("{ .reg .u64 t; cvta.to.shared.u64 t, %1; cvt.u32.u64 %0, t; }" : "=r"(a) : "l"(p));
    return a;
}
#define SWZ(o) ((o) ^ (((o) >> 3) & 0x70))

__device__ __forceinline__ void cp_async16(uint32_t dst, const void* src) {
    asm volatile("cp.async.cg.shared.global [%0], [%1], 16;" :: "r"(dst), "l"(src));
}
__device__ __forceinline__ void cp_commit() { asm volatile("cp.async.commit_group;"); }
__device__ __forceinline__ void cp_wait1()  { asm volatile("cp.async.wait_group 1;" ::: "memory"); }

__device__ __forceinline__ void ldsm_x4(uint32_t* r, uint32_t addr) {
    asm volatile("ldmatrix.sync.aligned.m8n8.x4.shared.b16 {%0,%1,%2,%3}, [%4];"
                 : "=r"(r[0]), "=r"(r[1]), "=r"(r[2]), "=r"(r[3]) : "r"(addr));
}
__device__ __forceinline__ void mma16816(float* d, const uint32_t* a, const uint32_t* b) {
    asm volatile(
        "mma.sync.aligned.m16n8k16.row.col.f32.f16.f16.f32 "
        "{%0,%1,%2,%3}, {%4,%5,%6,%7}, {%8,%9}, {%0,%1,%2,%3};"
        : "+f"(d[0]), "+f"(d[1]), "+f"(d[2]), "+f"(d[3])
        : "r"(a[0]), "r"(a[1]), "r"(a[2]), "r"(a[3]), "r"(b[0]), "r"(b[1]));
}
__device__ __forceinline__ int ld_flag(const int* p) {
    int v;
    asm volatile("ld.global.cg.b32 %0, [%1];" : "=r"(v) : "l"(p));
    return v;
}
__device__ __forceinline__ void red_add1(int* p) {
    asm volatile("red.global.add.s32 [%0], %1;" :: "l"(p), "r"(1) : "memory");
}
__device__ __forceinline__ void spin_flag(const int* p) {
    while (ld_flag(p) < TARGET) { asm volatile("nanosleep.u32 64;"); }
}

// ---------------- SMEM layout (per CTA) ----------------
#define A_BYTES (MT * 128)                         // 16384
#define B_BYTES (NT * 128)                         // 32768
#define STAGE_BYTES (A_BYTES + B_BYTES)            // 49152
#define SMEM_TOTAL (STAGES * STAGE_BYTES)          // 147456 -> 1 CTA/SM

// ---------------- flag reset (runs each launch; graph-replay determinism) ----
__global__ void zero_flags_kernel() {
    if (threadIdx.x < NCHUNK) g_flag[threadIdx.x] = 0;
}

// ---------------- conversion share: slice s, thread-unit u --------------------
// x: slice = 2048 rows x 16 float4 -> 32768 units.  w: 4096 rows x 16 int4 -> 65536 units.
// u in [0, GRID*THREADS) = [0, 75776) covers both with one unit max per thread.
__device__ __forceinline__ void conv_share(const float4* __restrict__ xg,
                                           const int4* __restrict__ wg,
                                           const float* __restrict__ sw,
                                           int s, int u) {
    if (u < 32768) {                       // x share
        const int r = u >> 4, c = u & 15;
        const int idx = r * 1024 + s * 16 + c;   // float4 / uint2 index
        float4 v = xg[idx];
        __half2 h0 = __floats2half2_rn(v.x, v.y);
        __half2 h1 = __floats2half2_rn(v.z, v.w);
        uint2 rr;
        rr.x = *reinterpret_cast<uint32_t*>(&h0);
        rr.y = *reinterpret_cast<uint32_t*>(&h1);
        reinterpret_cast<uint2*>(g_xh)[idx] = rr;
    }
    if (u < 65536) {                       // w share
        const int o = u >> 4, c = u & 15;
        const int g = s >> 1;
        int4 w = wg[o * 1024 + g * 32 + (s & 1) * 16 + c];
        const float sc = __ldg(&sw[(g << 12) + o]);
        __half2 h0 = __floats2half2_rn((float)w.x * sc, (float)w.y * sc);
        __half2 h1 = __floats2half2_rn((float)w.z * sc, (float)w.w * sc);
        uint2 rr;
        rr.x = *reinterpret_cast<uint32_t*>(&h0);
        rr.y = *reinterpret_cast<uint32_t*>(&h1);
        reinterpret_cast<uint2*>(g_wh)[o * 1024 + s * 16 + c] = rr;
    }
}

// ---------------- fused GEMM (persistent; conversion overlapped) -------------
__device__ __forceinline__ void load_chunk(uint32_t stage_base,
                                           const __half* Ag, const __half* Bg,
                                           int k0, int tid) {
    const uint32_t aB = stage_base;
    const uint32_t bB = stage_base + A_BYTES;
#pragma unroll
    for (int i = 0; i < 2; ++i) {          // A: 1024 units / 512 thr
        int uu = tid + i * THREADS;
        int row = uu >> 3, c = uu & 7;
        cp_async16(aB + SWZ(row * 128 + c * 16), Ag + (size_t)row * KDIM + k0 + c * 8);
    }
#pragma unroll
    for (int i = 0; i < 4; ++i) {          // B: 2048 units / 512 thr
        int uu = tid + i * THREADS;
        int row = uu >> 3, c = uu & 7;
        cp_async16(bB + SWZ(row * 128 + c * 16), Bg + (size_t)row * KDIM + k0 + c * 8);
    }
}

__global__ void __launch_bounds__(THREADS, 1)
gemm_kernel(const float4* __restrict__ xg, const int4* __restrict__ wg,
            const float* __restrict__ sw, const float* __restrict__ bias,
            float* __restrict__ out) {
    extern __shared__ __align__(128) char smem[];
    const uint32_t sb = smem_u32(smem);
    const int tid = threadIdx.x;
    const int wid = tid >> 5;
    const int lane = tid & 31;
    const int gid = lane >> 2;
    const int tig = lane & 3;
    const int u = blockIdx.x * THREADS + tid;   // conversion unit id

    // warp tile 64x32: wm {0,1}, wn {0..7}
    const int wm0 = (wid & 1) * 64;
    const int wn0 = (wid >> 1) * 32;
    // ldmatrix lane addressing (validated)
    const int a_row = wm0 + (lane & 7) + ((lane >> 3) & 1) * 8;
    const int a_kbo = ((lane >> 4) & 1) * 16;
    const int b_row = wn0 + (lane & 7) + ((lane >> 4) & 1) * 8;
    const int b_kbo = ((lane >> 3) & 1) * 16;

    // ---- conversion prologue: slices 0..7 ----
#pragma unroll
    for (int s = 0; s < 8; ++s) conv_share(xg, wg, sw, s, u);
    __threadfence();
    __syncthreads();
    if (tid == 0) {
#pragma unroll
        for (int s = 0; s < 8; ++s) red_add1(&g_flag[s]);
        spin_flag(&g_flag[0]);
        spin_flag(&g_flag[1]);
    }
    __syncthreads();
    int conv_cur = 8;   // next slice to convert (uniform)
    int arr = 8;        // next slice to arrive   (uniform)

    const int ntiles = (blockIdx.x + GRID < NTILES) ? 2 : 1;

    for (int t = 0; t < ntiles; ++t) {
        const int tile = blockIdx.x + t * GRID;
        const int m0 = (tile & 15) * MT;    // 16 m-tiles
        const int n0 = (tile >> 4) * NT;    // 16 n-tiles
        const __half* Ag = g_xh + (size_t)m0 * KDIM;
        const __half* Bg = g_wh + (size_t)n0 * KDIM;

        if (t) __syncthreads();   // protect smem stages before re-prologue
        load_chunk(sb + 0 * STAGE_BYTES, Ag, Bg, 0 * KC, tid);
        cp_commit();
        load_chunk(sb + 1 * STAGE_BYTES, Ag, Bg, 1 * KC, tid);
        cp_commit();

        float acc[4][4][4];
#pragma unroll
        for (int g = 0; g < 4; ++g)
#pragma unroll
            for (int j = 0; j < 4; ++j)
#pragma unroll
                for (int e = 0; e < 4; ++e) acc[g][j][e] = 0.0f;

        for (int kc = 0; kc < NCHUNK; ++kc) {
            cp_wait1();
            __syncthreads();

            if (t == 0 && kc < 62) {   // arrivals + gate for chunk kc+2
                if (tid == 0) {
                    for (int s = arr; s < conv_cur; ++s) red_add1(&g_flag[s]);
                    spin_flag(&g_flag[kc + 2]);
                }
                arr = conv_cur;
                __syncthreads();
            }

            {   // refill stage (kc+2)%3; empty commit at tail (uniform scheme)
                const int kn = kc + 2;
                if (kn < NCHUNK)
                    load_chunk(sb + (kn % STAGES) * STAGE_BYTES, Ag, Bg, kn * KC, tid);
                cp_commit();
            }

            if (t == 0 && conv_cur < NCHUNK) {   // convert 2 slices/iter, overlapped
                conv_share(xg, wg, sw, conv_cur, u);
                conv_share(xg, wg, sw, conv_cur + 1, u);
                __threadfence();
                conv_cur += 2;
            }

            const uint32_t stA = sb + (kc % STAGES) * STAGE_BYTES;
            const uint32_t stB = stA + A_BYTES;
#pragma unroll
            for (int ks = 0; ks < 4; ++ks) {
                uint32_t a[4][4], b[2][4];
#pragma unroll
                for (int g = 0; g < 4; ++g)
                    ldsm_x4(a[g], stA + SWZ((a_row + g * 16) * 128 + ks * 32 + a_kbo));
#pragma unroll
                for (int h = 0; h < 2; ++h)
                    ldsm_x4(b[h], stB + SWZ((b_row + h * 16) * 128 + ks * 32 + b_kbo));
#pragma unroll
                for (int g = 0; g < 4; ++g)
#pragma unroll
                    for (int h = 0; h < 2; ++h) {
                        mma16816(acc[g][2 * h + 0], a[g], &b[h][0]);
                        mma16816(acc[g][2 * h + 1], a[g], &b[h][2]);
                    }
            }
        }

        // epilogue
#pragma unroll
        for (int g = 0; g < 4; ++g) {
            const int row = m0 + wm0 + g * 16 + gid;
#pragma unroll
            for (int j = 0; j < 4; ++j) {
                const int bcol = wn0 + j * 8 + tig * 2;
                const float b0 = __ldg(&bias[n0 + bcol]);
                const float b1 = __ldg(&bias[n0 + bcol + 1]);
                float* op = out + (size_t)row * NDIM + n0 + bcol;
                float2 v0 = {acc[g][j][0] + b0, acc[g][j][1] + b1};
                float2 v1 = {acc[g][j][2] + b0, acc[g][j][3] + b1};
                *reinterpret_cast<float2*>(op) = v0;
                *reinterpret_cast<float2*>(op + 8 * NDIM) = v1;
            }
        }
    }
}

// ---------------- launch ----------------
extern "C" void kernel_launch(void* const* d_in, const int* in_sizes, int n_in,
                              void* d_out, int out_size) {
    const float* x    = (const float*)d_in[0];
    const int*   wq   = (const int*)d_in[1];    // int8 promoted to int32 on the wire
    const float* sw   = (const float*)d_in[2];
    const float* bias = (const float*)d_in[3];
    float*       out  = (float*)d_out;

    zero_flags_kernel<<<1, 64>>>();

    cudaFuncSetAttribute(gemm_kernel, cudaFuncAttributeMaxDynamicSharedMemorySize, SMEM_TOTAL);
    gemm_kernel<<<GRID, THREADS, SMEM_TOTAL>>>((const float4*)x, (const int4*)wq,
                                               sw, bias, out);
}

// round 14
// speedup vs baseline: 1.0865x; 1.0865x over previous
#include <cuda_runtime.h>
#include <cuda_fp16.h>
#include <cstdint>

// Problem sizes (fixed)
#define MDIM 2048
#define NDIM 4096
#define KDIM 4096
// Tiling
#define MT 128        // CTA tile M
#define NT 128        // CTA tile N
#define KC 64         // K-chunk (halves) = 128B per smem row
#define NCHUNK (KDIM / KC)   // 64
#define STAGES 3
#define THREADS 256

// Scratch (allocation-free rule: __device__ globals)
__device__ __half g_xh[(size_t)MDIM * KDIM];  // 16 MB
__device__ __half g_wh[(size_t)NDIM * KDIM];  // 32 MB

// ---------------- helpers ----------------
__device__ __forceinline__ uint32_t smem_u32(const void* p) {
    uint32_t a;
    asm("{ .reg .u64 t; cvta.to.shared.u64 t, %1; cvt.u32.u64 %0, t; }" : "=r"(a) : "l"(p));
    return a;
}
// SW128 XOR swizzle [proven]
#define SWZ(o) ((o) ^ (((o) >> 3) & 0x70))

__device__ __forceinline__ void cp_async16(uint32_t dst, const void* src) {
    asm volatile("cp.async.cg.shared.global [%0], [%1], 16;" :: "r"(dst), "l"(src));
}
__device__ __forceinline__ void cp_commit() { asm volatile("cp.async.commit_group;"); }
__device__ __forceinline__ void cp_wait1()  { asm volatile("cp.async.wait_group 1;" ::: "memory"); }

__device__ __forceinline__ void ldsm_x4(uint32_t* r, uint32_t addr) {
    asm volatile("ldmatrix.sync.aligned.m8n8.x4.shared.b16 {%0,%1,%2,%3}, [%4];"
                 : "=r"(r[0]), "=r"(r[1]), "=r"(r[2]), "=r"(r[3]) : "r"(addr));
}
// fp16-accumulate MMA: d,c are 2x f16x2 regs.
// d reg0 = (row gid, cols tig*2,+1), reg1 = (row gid+8, same cols)
__device__ __forceinline__ void mma16816_f16(uint32_t* d, const uint32_t* a, const uint32_t* b) {
    asm volatile(
        "mma.sync.aligned.m16n8k16.row.col.f16.f16.f16.f16 "
        "{%0,%1}, {%2,%3,%4,%5}, {%6,%7}, {%0,%1};"
        : "+r"(d[0]), "+r"(d[1])
        : "r"(a[0]), "r"(a[1]), "r"(a[2]), "r"(a[3]), "r"(b[0]), "r"(b[1]));
}

// ---------------- SMEM layout (per CTA) ----------------
#define OFF_BIAS 0                                 // 128 floats
#define OFF_A 1024
#define A_BYTES (MT * 128)                         // 16384
#define B_BYTES (NT * 128)                         // 16384
#define STAGE_BYTES (A_BYTES + B_BYTES)            // 32768
#define SMEM_TOTAL (OFF_A + STAGES * STAGE_BYTES)  // 99328

// ---------------- fused conversion kernel (proven R8) ----------------
#define CONV_ILP 8
#define XUNITS (MDIM * KDIM / 4)
#define WUNITS (NDIM * KDIM / 4)
#define XBLK (XUNITS / (THREADS * CONV_ILP))   // 1024
#define WBLK (WUNITS / (THREADS * CONV_ILP))   // 2048

__global__ void conv_fused_kernel(const float4* __restrict__ x,
                                  const int4* __restrict__ wq,
                                  const float* __restrict__ sw) {
    const int tid = threadIdx.x;
    if (blockIdx.x < XBLK) {
        const int base = blockIdx.x * (THREADS * CONV_ILP) + tid;
        float4 v[CONV_ILP];
#pragma unroll
        for (int j = 0; j < CONV_ILP; ++j) v[j] = x[base + j * THREADS];
#pragma unroll
        for (int j = 0; j < CONV_ILP; ++j) {
            __half2 h0 = __floats2half2_rn(v[j].x, v[j].y);
            __half2 h1 = __floats2half2_rn(v[j].z, v[j].w);
            uint2 r;
            r.x = *reinterpret_cast<uint32_t*>(&h0);
            r.y = *reinterpret_cast<uint32_t*>(&h1);
            reinterpret_cast<uint2*>(g_xh)[base + j * THREADS] = r;
        }
    } else {
        const int base = (blockIdx.x - XBLK) * (THREADS * CONV_ILP) + tid;
        int4 w[CONV_ILP];
#pragma unroll
        for (int j = 0; j < CONV_ILP; ++j) w[j] = wq[base + j * THREADS];
#pragma unroll
        for (int j = 0; j < CONV_ILP; ++j) {
            const int i = base + j * THREADS;
            const int idx4 = i << 2;
            const int o = idx4 >> 12;          // w_q (o,g,k): o*4096 + g*128 + k
            const int g = (idx4 >> 7) & 31;
            const float s = __ldg(&sw[(g << 12) + o]);  // s_w (g,o)
            __half2 h0 = __floats2half2_rn((float)w[j].x * s, (float)w[j].y * s);
            __half2 h1 = __floats2half2_rn((float)w[j].z * s, (float)w[j].w * s);
            uint2 r;
            r.x = *reinterpret_cast<uint32_t*>(&h0);
            r.y = *reinterpret_cast<uint32_t*>(&h1);
            reinterpret_cast<uint2*>(g_wh)[i] = r;
        }
    }
}

// ---------------- GEMM: R8 geometry, fp16 acc + fp32 master every 2 chunks ----
__device__ __forceinline__ void load_chunk(uint32_t stage_base,
                                           const __half* Ag, const __half* Bg,
                                           int k0, int tid) {
    const uint32_t aB = stage_base;
    const uint32_t bB = stage_base + A_BYTES;
#pragma unroll
    for (int i = 0; i < 4; ++i) {
        int u = tid + i * THREADS;
        int row = u >> 3, c = u & 7;
        cp_async16(aB + SWZ(row * 128 + c * 16), Ag + (size_t)row * KDIM + k0 + c * 8);
    }
#pragma unroll
    for (int i = 0; i < 4; ++i) {
        int u = tid + i * THREADS;
        int row = u >> 3, c = u & 7;
        cp_async16(bB + SWZ(row * 128 + c * 16), Bg + (size_t)row * KDIM + k0 + c * 8);
    }
}

__global__ void __launch_bounds__(THREADS, 1)
gemm_kernel(const float* __restrict__ bias, float* __restrict__ out) {
    extern __shared__ __align__(128) char smem[];
    const uint32_t sb = smem_u32(smem);
    const int tid = threadIdx.x;
    const int wid = tid >> 5;
    const int lane = tid & 31;
    const int gid = lane >> 2;
    const int tig = lane & 3;

    // bm fast-varying so consecutive CTAs share the B tile in L2
    const int bm = blockIdx.x & 15;   // 16 m-tiles
    const int bn = blockIdx.x >> 4;   // 32 n-tiles
    const int m0 = bm * MT;
    const int n0 = bn * NT;

    // warp tile: 64x32
    const int wm0 = (wid & 1) * 64;
    const int wn0 = (wid >> 1) * 32;

    if (tid < NT) ((float*)(smem + OFF_BIAS))[tid] = bias[n0 + tid];

    const __half* Ag = g_xh + (size_t)m0 * KDIM;
    const __half* Bg = g_wh + (size_t)n0 * KDIM;

#pragma unroll
    for (int s = 0; s < STAGES - 1; ++s) {
        load_chunk(sb + OFF_A + s * STAGE_BYTES, Ag, Bg, s * KC, tid);
        cp_commit();
    }

    // fp32 master accumulators + fp16 partial accumulators (reset every 2 chunks)
    float facc[4][4][4];
    uint32_t hacc[4][4][2];
#pragma unroll
    for (int g = 0; g < 4; ++g)
#pragma unroll
        for (int j = 0; j < 4; ++j) {
#pragma unroll
            for (int e = 0; e < 4; ++e) facc[g][j][e] = 0.0f;
            hacc[g][j][0] = 0u; hacc[g][j][1] = 0u;
        }

    // ldmatrix lane addressing (validated)
    const int a_row = wm0 + (lane & 7) + ((lane >> 3) & 1) * 8;  // + g*16
    const int a_kbo = ((lane >> 4) & 1) * 16;                    // + ks*32
    const int b_row = wn0 + (lane & 7) + ((lane >> 4) & 1) * 8;  // + h*16
    const int b_kbo = ((lane >> 3) & 1) * 16;                    // + ks*32

    for (int kc = 0; kc < NCHUNK; ++kc) {
        cp_wait1();
        __syncthreads();

        {   // refill stage (kc+2)%3 with chunk kc+2; empty commit at tail
            const int kn = kc + STAGES - 1;
            if (kn < NCHUNK)
                load_chunk(sb + OFF_A + (kn % STAGES) * STAGE_BYTES, Ag, Bg, kn * KC, tid);
            cp_commit();
        }

        const uint32_t stA = sb + OFF_A + (kc % STAGES) * STAGE_BYTES;
        const uint32_t stB = stA + A_BYTES;
#pragma unroll
        for (int ks = 0; ks < 4; ++ks) {
            uint32_t a[4][4], b[2][4];
#pragma unroll
            for (int g = 0; g < 4; ++g)
                ldsm_x4(a[g], stA + SWZ((a_row + g * 16) * 128 + ks * 32 + a_kbo));
#pragma unroll
            for (int h = 0; h < 2; ++h)
                ldsm_x4(b[h], stB + SWZ((b_row + h * 16) * 128 + ks * 32 + b_kbo));
#pragma unroll
            for (int g = 0; g < 4; ++g)
#pragma unroll
                for (int h = 0; h < 2; ++h) {
                    mma16816_f16(hacc[g][2 * h + 0], a[g], &b[h][0]);  // n cols h*16+0..7
                    mma16816_f16(hacc[g][2 * h + 1], a[g], &b[h][2]);  // n cols h*16+8..15
                }
        }

        if (kc & 1) {   // promote fp16 partials (2 chunks = K=128) into fp32 masters
#pragma unroll
            for (int g = 0; g < 4; ++g)
#pragma unroll
                for (int j = 0; j < 4; ++j) {
                    float2 lo = __half22float2(*reinterpret_cast<__half2*>(&hacc[g][j][0]));
                    float2 hi = __half22float2(*reinterpret_cast<__half2*>(&hacc[g][j][1]));
                    facc[g][j][0] += lo.x; facc[g][j][1] += lo.y;
                    facc[g][j][2] += hi.x; facc[g][j][3] += hi.y;
                    hacc[g][j][0] = 0u; hacc[g][j][1] = 0u;
                }
        }
    }

    // epilogue: c0,c1 at (row=gid, col=tig*2..+1), c2,c3 at row+8
    const float* bsm = (const float*)(smem + OFF_BIAS);
#pragma unroll
    for (int g = 0; g < 4; ++g) {
        const int row = m0 + wm0 + g * 16 + gid;
#pragma unroll
        for (int j = 0; j < 4; ++j) {
            const int bcol = wn0 + j * 8 + tig * 2;
            const float b0 = bsm[bcol], b1 = bsm[bcol + 1];
            float* op = out + (size_t)row * NDIM + n0 + bcol;
            float2 v0 = {facc[g][j][0] + b0, facc[g][j][1] + b1};
            float2 v1 = {facc[g][j][2] + b0, facc[g][j][3] + b1};
            *reinterpret_cast<float2*>(op) = v0;
            *reinterpret_cast<float2*>(op + 8 * NDIM) = v1;
        }
    }
}

// ---------------- launch ----------------
extern "C" void kernel_launch(void* const* d_in, const int* in_sizes, int n_in,
                              void* d_out, int out_size) {
    const float* x    = (const float*)d_in[0];
    const int*   wq   = (const int*)d_in[1];    // int8 promoted to int32 on the wire
    const float* sw   = (const float*)d_in[2];
    const float* bias = (const float*)d_in[3];
    float*       out  = (float*)d_out;

    conv_fused_kernel<<<XBLK + WBLK, THREADS>>>((const float4*)x, (const int4*)wq, sw);

    cudaFuncSetAttribute(gemm_kernel, cudaFuncAttributeMaxDynamicSharedMemorySize, SMEM_TOTAL);
    gemm_kernel<<<(MDIM / MT) * (NDIM / NT), THREADS, SMEM_TOTAL>>>(bias, out);
}

// round 16
// speedup vs baseline: 1.4197x; 1.3067x over previous
#include <cuda_runtime.h>
#include <cuda_fp16.h>
#include <cstdint>

// Problem sizes (fixed)
#define MDIM 2048
#define NDIM 4096
#define KDIM 4096
// Tiling
#define MT 128        // CTA tile M
#define NT 128        // CTA tile N
#define KC 64         // K-chunk (halves) = 128B per smem row
#define NCHUNK (KDIM / KC)   // 64
#define STAGES 3
#define THREADS 256

// Scratch (allocation-free rule: __device__ globals)
__device__ __half g_xh[(size_t)MDIM * KDIM];  // 16 MB
__device__ __half g_wh[(size_t)NDIM * KDIM];  // 32 MB

// ---------------- helpers ----------------
__device__ __forceinline__ uint32_t smem_u32(const void* p) {
    uint32_t a;
    asm("{ .reg .u64 t; cvta.to.shared.u64 t, %1; cvt.u32.u64 %0, t; }" : "=r"(a) : "l"(p));
    return a;
}
// SW128: XOR 16B-chunk index (bits 4-6) with row%8 (bits 7-9)  [proven]
#define SWZ(o) ((o) ^ (((o) >> 3) & 0x70))

__device__ __forceinline__ void cp_async16(uint32_t dst, const void* src) {
    asm volatile("cp.async.cg.shared.global [%0], [%1], 16;" :: "r"(dst), "l"(src));
}
__device__ __forceinline__ void cp_commit() { asm volatile("cp.async.commit_group;"); }
__device__ __forceinline__ void cp_wait1()  { asm volatile("cp.async.wait_group 1;" ::: "memory"); }

__device__ __forceinline__ void ldsm_x4(uint32_t* r, uint32_t addr) {
    asm volatile("ldmatrix.sync.aligned.m8n8.x4.shared.b16 {%0,%1,%2,%3}, [%4];"
                 : "=r"(r[0]), "=r"(r[1]), "=r"(r[2]), "=r"(r[3]) : "r"(addr));
}
__device__ __forceinline__ void mma16816(float* d, const uint32_t* a, const uint32_t* b) {
    asm volatile(
        "mma.sync.aligned.m16n8k16.row.col.f32.f16.f16.f32 "
        "{%0,%1,%2,%3}, {%4,%5,%6,%7}, {%8,%9}, {%0,%1,%2,%3};"
        : "+f"(d[0]), "+f"(d[1]), "+f"(d[2]), "+f"(d[3])
        : "r"(a[0]), "r"(a[1]), "r"(a[2]), "r"(a[3]), "r"(b[0]), "r"(b[1]));
}
// L2-resident streaming store (conv outputs are re-read by the GEMM shortly after)
__device__ __forceinline__ void stg_cg8(void* p, uint2 v) {
    asm volatile("st.global.cg.v2.b32 [%0], {%1, %2};" :: "l"(p), "r"(v.x), "r"(v.y) : "memory");
}

// ---------------- SMEM layout (per CTA) ----------------
#define OFF_BIAS 0                                 // 128 floats
#define OFF_A 1024
#define A_BYTES (MT * 128)                         // 16384
#define B_BYTES (NT * 128)                         // 16384
#define STAGE_BYTES (A_BYTES + B_BYTES)            // 32768
#define SMEM_TOTAL (OFF_A + STAGES * STAGE_BYTES)  // 99328 -> 2 CTAs/SM

// ---------------- fused conversion kernel ----------------
// Blocks [0, XBLK): fp32 x -> fp16 (8 float4 units/thread)
// Blocks [XBLK, XBLK+WBLK): int32 w * scale -> fp16 (8 int4 units/thread)
#define CONV_ILP 8
#define XUNITS (MDIM * KDIM / 4)          // 2,097,152 float4 units
#define WUNITS (NDIM * KDIM / 4)          // 4,194,304 int4 units
#define XBLK (XUNITS / (THREADS * CONV_ILP))   // 1024
#define WBLK (WUNITS / (THREADS * CONV_ILP))   // 2048

__global__ void conv_fused_kernel(const float4* __restrict__ x,
                                  const int4* __restrict__ wq,
                                  const float* __restrict__ sw) {
    const int tid = threadIdx.x;
    if (blockIdx.x < XBLK) {
        const int base = blockIdx.x * (THREADS * CONV_ILP) + tid;
        float4 v[CONV_ILP];
#pragma unroll
        for (int j = 0; j < CONV_ILP; ++j) v[j] = x[base + j * THREADS];
#pragma unroll
        for (int j = 0; j < CONV_ILP; ++j) {
            __half2 h0 = __floats2half2_rn(v[j].x, v[j].y);
            __half2 h1 = __floats2half2_rn(v[j].z, v[j].w);
            uint2 r;
            r.x = *reinterpret_cast<uint32_t*>(&h0);
            r.y = *reinterpret_cast<uint32_t*>(&h1);
            stg_cg8(reinterpret_cast<uint2*>(g_xh) + base + j * THREADS, r);
        }
    } else {
        const int base = (blockIdx.x - XBLK) * (THREADS * CONV_ILP) + tid;
        int4 w[CONV_ILP];
#pragma unroll
        for (int j = 0; j < CONV_ILP; ++j) w[j] = wq[base + j * THREADS];
#pragma unroll
        for (int j = 0; j < CONV_ILP; ++j) {
            const int i = base + j * THREADS;
            const int idx4 = i << 2;
            const int o = idx4 >> 12;          // w_q (o,g,k): o*4096 + g*128 + k
            const int g = (idx4 >> 7) & 31;
            const float s = __ldg(&sw[(g << 12) + o]);  // s_w (g,o)
            __half2 h0 = __floats2half2_rn((float)w[j].x * s, (float)w[j].y * s);
            __half2 h1 = __floats2half2_rn((float)w[j].z * s, (float)w[j].w * s);
            uint2 r;
            r.x = *reinterpret_cast<uint32_t*>(&h0);
            r.y = *reinterpret_cast<uint32_t*>(&h1);
            stg_cg8(reinterpret_cast<uint2*>(g_wh) + i, r);
        }
    }
}

// ---------------- GEMM (R8 champion — proven 177 us) ----------------
__device__ __forceinline__ void load_chunk(uint32_t stage_base,
                                           const __half* Ag, const __half* Bg,
                                           int k0, int tid) {
    const uint32_t aB = stage_base;
    const uint32_t bB = stage_base + A_BYTES;
#pragma unroll
    for (int i = 0; i < 4; ++i) {
        int u = tid + i * THREADS;
        int row = u >> 3, c = u & 7;
        cp_async16(aB + SWZ(row * 128 + c * 16), Ag + (size_t)row * KDIM + k0 + c * 8);
    }
#pragma unroll
    for (int i = 0; i < 4; ++i) {
        int u = tid + i * THREADS;
        int row = u >> 3, c = u & 7;
        cp_async16(bB + SWZ(row * 128 + c * 16), Bg + (size_t)row * KDIM + k0 + c * 8);
    }
}

__global__ void __launch_bounds__(THREADS, 2)
gemm_kernel(const float* __restrict__ bias, float* __restrict__ out) {
    extern __shared__ __align__(128) char smem[];
    const uint32_t sb = smem_u32(smem);
    const int tid = threadIdx.x;
    const int wid = tid >> 5;
    const int lane = tid & 31;
    const int gid = lane >> 2;   // groupID (0..7)
    const int tig = lane & 3;    // thread-in-group

    // bm fast-varying so consecutive CTAs share the B tile in L2
    const int bm = blockIdx.x & 15;   // 16 m-tiles
    const int bn = blockIdx.x >> 4;   // 32 n-tiles
    const int m0 = bm * MT;
    const int n0 = bn * NT;

    // warp tile: 64x32
    const int wm0 = (wid & 1) * 64;
    const int wn0 = (wid >> 1) * 32;

    if (tid < NT) ((float*)(smem + OFF_BIAS))[tid] = bias[n0 + tid];

    const __half* Ag = g_xh + (size_t)m0 * KDIM;
    const __half* Bg = g_wh + (size_t)n0 * KDIM;

#pragma unroll
    for (int s = 0; s < STAGES - 1; ++s) {
        load_chunk(sb + OFF_A + s * STAGE_BYTES, Ag, Bg, s * KC, tid);
        cp_commit();
    }

    float acc[4][4][4];
#pragma unroll
    for (int g = 0; g < 4; ++g)
#pragma unroll
        for (int j = 0; j < 4; ++j)
#pragma unroll
            for (int e = 0; e < 4; ++e) acc[g][j][e] = 0.0f;

    // ldmatrix lane addressing (validated)
    const int a_row = wm0 + (lane & 7) + ((lane >> 3) & 1) * 8;  // + g*16
    const int a_kbo = ((lane >> 4) & 1) * 16;                    // + ks*32
    const int b_row = wn0 + (lane & 7) + ((lane >> 4) & 1) * 8;  // + h*16
    const int b_kbo = ((lane >> 3) & 1) * 16;                    // + ks*32

    for (int kc = 0; kc < NCHUNK; ++kc) {
        cp_wait1();        // chunk kc landed (uniform one-commit-per-iter scheme)
        __syncthreads();   // all warps done with the stage about to be refilled

        {   // refill stage (kc+2)%3 with chunk kc+2; empty commit at tail
            const int kn = kc + STAGES - 1;
            if (kn < NCHUNK)
                load_chunk(sb + OFF_A + (kn % STAGES) * STAGE_BYTES, Ag, Bg, kn * KC, tid);
            cp_commit();
        }

        const uint32_t stA = sb + OFF_A + (kc % STAGES) * STAGE_BYTES;
        const uint32_t stB = stA + A_BYTES;
#pragma unroll
        for (int ks = 0; ks < 4; ++ks) {
            uint32_t a[4][4], b[2][4];
#pragma unroll
            for (int g = 0; g < 4; ++g)
                ldsm_x4(a[g], stA + SWZ((a_row + g * 16) * 128 + ks * 32 + a_kbo));
#pragma unroll
            for (int h = 0; h < 2; ++h)
                ldsm_x4(b[h], stB + SWZ((b_row + h * 16) * 128 + ks * 32 + b_kbo));
#pragma unroll
            for (int g = 0; g < 4; ++g)
#pragma unroll
                for (int h = 0; h < 2; ++h) {
                    mma16816(acc[g][2 * h + 0], a[g], &b[h][0]);  // n cols h*16+0..7
                    mma16816(acc[g][2 * h + 1], a[g], &b[h][2]);  // n cols h*16+8..15
                }
        }
    }

    // epilogue: per mma, c0,c1 at (row=gid, col=tig*2..+1), c2,c3 at row+8
    const float* bsm = (const float*)(smem + OFF_BIAS);
#pragma unroll
    for (int g = 0; g < 4; ++g) {
        const int row = m0 + wm0 + g * 16 + gid;
#pragma unroll
        for (int j = 0; j < 4; ++j) {
            const int bcol = wn0 + j * 8 + tig * 2;
            const float b0 = bsm[bcol], b1 = bsm[bcol + 1];
            float* op = out + (size_t)row * NDIM + n0 + bcol;
            float2 v0 = {acc[g][j][0] + b0, acc[g][j][1] + b1};
            float2 v1 = {acc[g][j][2] + b0, acc[g][j][3] + b1};
            *reinterpret_cast<float2*>(op) = v0;
            *reinterpret_cast<float2*>(op + 8 * NDIM) = v1;
        }
    }
}

// ---------------- launch ----------------
extern "C" void kernel_launch(void* const* d_in, const int* in_sizes, int n_in,
                              void* d_out, int out_size) {
    const float* x    = (const float*)d_in[0];
    const int*   wq   = (const int*)d_in[1];    // int8 promoted to int32 on the wire
    const float* sw   = (const float*)d_in[2];
    const float* bias = (const float*)d_in[3];
    float*       out  = (float*)d_out;

    conv_fused_kernel<<<XBLK + WBLK, THREADS>>>((const float4*)x, (const int4*)wq, sw);

    cudaFuncSetAttribute(gemm_kernel, cudaFuncAttributeMaxDynamicSharedMemorySize, SMEM_TOTAL);
    gemm_kernel<<<(MDIM / MT) * (NDIM / NT), THREADS, SMEM_TOTAL>>>(bias, out);
}